// round 1
// baseline (speedup 1.0000x reference)
#include <cuda_runtime.h>
#include <cuda_fp16.h>

#define HH 128
#define WW 128
#define CC 256
#define BB 4
#define NROI 512

// 64 MB NHWC scratch (static device global: allowed; no dynamic allocation)
__device__ float g_nhwc[(size_t)BB * HH * WW * CC];

// ---------------------------------------------------------------------------
// Kernel 1: NCHW -> NHWC transpose. Per batch: transpose [C=256, HW=16384]
// to [HW, C] using 32x32 shared tiles. Fully coalesced both sides.
// ---------------------------------------------------------------------------
__global__ __launch_bounds__(256) void nchw_to_nhwc(const float* __restrict__ in) {
    __shared__ float tile[32][33];
    const int b  = blockIdx.z;
    const int p0 = blockIdx.x * 32;   // pixel tile base (HW dim)
    const int c0 = blockIdx.y * 32;   // channel tile base
    const int tx = threadIdx.x;       // 0..31
    const int ty = threadIdx.y;       // 0..7

    const float* src = in + (size_t)b * CC * HH * WW;
#pragma unroll
    for (int i = 0; i < 32; i += 8)
        tile[ty + i][tx] = src[(size_t)(c0 + ty + i) * (HH * WW) + p0 + tx];
    __syncthreads();
    float* dst = g_nhwc + (size_t)b * HH * WW * CC;
#pragma unroll
    for (int i = 0; i < 32; i += 8)
        dst[(size_t)(p0 + ty + i) * CC + c0 + tx] = tile[tx][ty + i];
}

// ---------------------------------------------------------------------------
// Kernel 2: one block per ROI. Build separable per-axis weight lists
// (<= 28 rows, <= 28 cols), then accumulate Wy[r]*Wx[c]*F[b,r,c,ch] for all
// 256 channels via float4 loads. 4-way pixel slicing across the 256 threads
// for memory-level parallelism, reduced through shared memory at the end.
// ---------------------------------------------------------------------------
__global__ __launch_bounds__(256) void roi_pool_kernel(const float* __restrict__ rois,
                                                       float* __restrict__ out) {
    const int roi = blockIdx.x;
    const int t   = threadIdx.x;

    __shared__ float dy[HH];
    __shared__ float dx[WW];
    __shared__ int   s_rows[32];
    __shared__ float s_rw[32];
    __shared__ int   s_cols[32];
    __shared__ float s_cw[32];
    __shared__ int   s_nr, s_nc, s_b;
    __shared__ float4 s_part[4][64];

    // zero dense per-axis weight maps
    if (t < 128) { dy[t] = 0.0f; dx[t] = 0.0f; }
    __syncthreads();

    // Thread 0 builds the y-axis weights, thread 32 the x-axis weights
    // (different warps -> concurrent). Both recompute the cheap ROI params.
    if (t == 0 || t == 32) {
        const float* R = rois + roi * 6;
        const float cx = R[2], cy = R[3], rw_ = R[4], rh_ = R[5];
        // Replicate: f16 round of ((c +/- 0.5*s) * 128)
        const float x1f = __half2float(__float2half_rn((cx - 0.5f * rw_) * 128.0f));
        const float y1f = __half2float(__float2half_rn((cy - 0.5f * rh_) * 128.0f));
        const float x2f = __half2float(__float2half_rn((cx + 0.5f * rw_) * 128.0f));
        const float y2f = __half2float(__float2half_rn((cy + 0.5f * rh_) * 128.0f));
        const float roi_w = fmaxf(x2f - x1f, 1.0f);
        const float roi_h = fmaxf(y2f - y1f, 1.0f);

        if (t == 0) {
            s_b = (int)R[0];
            const float sw = __fdiv_rn(roi_h, 7.0f);
            for (int k = 0; k < 14; k++) {
                const float off = (float)(k >> 1) + ((k & 1) ? 0.75f : 0.25f);
                const float ys = __fadd_rn(y1f, __fmul_rn(off, sw));
                if (ys > -1.0f && ys < 128.0f) {
                    const float yc = fminf(fmaxf(ys, 0.0f), 127.0f);
                    const int y0 = (int)floorf(yc);
                    const int y1i = min(y0 + 1, 127);
                    const float ly = yc - (float)y0;
                    dy[y0]  += 1.0f - ly;
                    dy[y1i] += ly;
                }
            }
            int n = 0;
            for (int r = 0; r < 128; r++) {
                const float w = dy[r];
                if (w != 0.0f) { s_rows[n] = r; s_rw[n] = w; n++; }
            }
            s_nr = n;
        } else {
            const float sw = __fdiv_rn(roi_w, 7.0f);
            for (int k = 0; k < 14; k++) {
                const float off = (float)(k >> 1) + ((k & 1) ? 0.75f : 0.25f);
                const float xs = __fadd_rn(x1f, __fmul_rn(off, sw));
                if (xs > -1.0f && xs < 128.0f) {
                    const float xc = fminf(fmaxf(xs, 0.0f), 127.0f);
                    const int x0 = (int)floorf(xc);
                    const int x1i = min(x0 + 1, 127);
                    const float lx = xc - (float)x0;
                    dx[x0]  += 1.0f - lx;
                    dx[x1i] += lx;
                }
            }
            int n = 0;
            for (int c = 0; c < 128; c++) {
                const float w = dx[c];
                if (w != 0.0f) { s_cols[n] = c; s_cw[n] = w; n++; }
            }
            s_nc = n;
        }
    }
    __syncthreads();

    // Main accumulation: thread t handles channels [4*(t&63) .. +3] and the
    // pixel slice (t>>6) of the footprint columns.
    const int slice = t >> 6;           // 0..3
    const int chg   = (t & 63) << 2;    // channel base (float4)
    const int nr = s_nr, nc = s_nc;
    const float* base = g_nhwc + (size_t)s_b * (HH * WW) * CC + chg;

    float4 acc = make_float4(0.0f, 0.0f, 0.0f, 0.0f);
    for (int r = 0; r < nr; r++) {
        const float* rowp = base + (size_t)(s_rows[r] * WW) * CC;
        const float rw = s_rw[r];
#pragma unroll 2
        for (int c = slice; c < nc; c += 4) {
            const float w = rw * s_cw[c];
            const float4 v = *(const float4*)(rowp + (size_t)s_cols[c] * CC);
            acc.x += w * v.x;
            acc.y += w * v.y;
            acc.z += w * v.z;
            acc.w += w * v.w;
        }
    }

    s_part[slice][t & 63] = acc;
    __syncthreads();

    if (t < 64) {
        const float4 a0 = s_part[0][t];
        const float4 a1 = s_part[1][t];
        const float4 a2 = s_part[2][t];
        const float4 a3 = s_part[3][t];
        float4 s;
        s.x = (a0.x + a1.x + a2.x + a3.x) / 196.0f;
        s.y = (a0.y + a1.y + a2.y + a3.y) / 196.0f;
        s.z = (a0.z + a1.z + a2.z + a3.z) / 196.0f;
        s.w = (a0.w + a1.w + a2.w + a3.w) / 196.0f;
        ((float4*)(out + (size_t)roi * CC))[t] = s;
    }
    if (t == 0) {
        // gt = rois[:, 1], appended after the (512, 256) features
        out[(size_t)NROI * CC + roi] = rois[roi * 6 + 1];
    }
}

// ---------------------------------------------------------------------------
extern "C" void kernel_launch(void* const* d_in, const int* in_sizes, int n_in,
                              void* d_out, int out_size) {
    const float* feature_map = (const float*)d_in[0];
    const float* rois        = (const float*)d_in[1];
    float* out = (float*)d_out;

    dim3 tb(32, 8);
    dim3 tg((HH * WW) / 32, CC / 32, BB);   // (512, 8, 4)
    nchw_to_nhwc<<<tg, tb>>>(feature_map);

    roi_pool_kernel<<<NROI, 256>>>(rois, out);
    (void)in_sizes; (void)n_in; (void)out_size;
}

// round 6
// speedup vs baseline: 1.6423x; 1.6423x over previous
#include <cuda_runtime.h>
#include <cuda_fp16.h>

#define HH 128
#define WW 128
#define CC 256
#define BB 4
#define NROI 512
#define NSL 4     // row slices  (blockIdx.y)
#define NCS 8     // col slices  (within block)

// 32 MB fp16 NHWC scratch + 2 MB partial-sum buffer (static device globals)
__device__ __half g_nhwc_h[(size_t)BB * HH * WW * CC];
__device__ float  g_part[(size_t)NROI * NSL * CC];

// ---------------------------------------------------------------------------
// Kernel 1: NCHW fp32 -> NHWC fp16 transpose via 32x32 shared tiles.
// ---------------------------------------------------------------------------
__global__ __launch_bounds__(256) void nchw_to_nhwc_h(const float* __restrict__ in) {
    __shared__ float tile[32][33];
    const int b  = blockIdx.z;
    const int p0 = blockIdx.x * 32;   // pixel tile base (HW dim)
    const int c0 = blockIdx.y * 32;   // channel tile base
    const int tx = threadIdx.x;       // 0..31
    const int ty = threadIdx.y;       // 0..7

    const float* src = in + (size_t)b * CC * HH * WW;
#pragma unroll
    for (int i = 0; i < 32; i += 8)
        tile[ty + i][tx] = src[(size_t)(c0 + ty + i) * (HH * WW) + p0 + tx];
    __syncthreads();
    __half* dst = g_nhwc_h + (size_t)b * HH * WW * CC;
#pragma unroll
    for (int i = 0; i < 32; i += 8)
        dst[(size_t)(p0 + ty + i) * CC + c0 + tx] = __float2half_rn(tile[tx][ty + i]);
}

// ---------------------------------------------------------------------------
// Kernel 2: block (roi, s) computes partial sums over row-slice s of the ROI
// footprint, all 256 channels, into g_part. Weight lists built in parallel
// (bit-identical FP order to the reference) + deterministic ballot compaction.
// ---------------------------------------------------------------------------
__global__ __launch_bounds__(256, 6) void roi_partial_kernel(const float* __restrict__ rois) {
    const int roi = blockIdx.x;
    const int s   = blockIdx.y;      // row slice 0..3
    const int t   = threadIdx.x;

    __shared__ int   s_rows[32];
    __shared__ float s_rw[32];
    __shared__ int   s_cols[32];
    __shared__ float s_cw[32];
    __shared__ int   s_cnt[2];
    __shared__ int   s_warpoff[8];
    __shared__ float s_part[NCS * CC];   // 8 KB

    // --- ROI params (every thread, cheap; same FP ops as reference) ---------
    const float* R = rois + roi * 6;
    const int   b   = (int)R[0];
    const float cx  = R[2], cy = R[3], rw_ = R[4], rh_ = R[5];
    const float x1f = __half2float(__float2half_rn((cx - 0.5f * rw_) * 128.0f));
    const float y1f = __half2float(__float2half_rn((cy - 0.5f * rh_) * 128.0f));
    const float x2f = __half2float(__float2half_rn((cx + 0.5f * rw_) * 128.0f));
    const float y2f = __half2float(__float2half_rn((cy + 0.5f * rh_) * 128.0f));
    const float roi_w = fmaxf(x2f - x1f, 1.0f);
    const float roi_h = fmaxf(y2f - y1f, 1.0f);

    // --- Per-thread axis weight: threads 0-127 -> rows, 128-255 -> cols -----
    {
        const int   axis  = t >> 7;          // 0 = y (rows), 1 = x (cols)
        const int   idx   = t & 127;
        const float start = axis ? x1f : y1f;
        const float sw    = __fdiv_rn(axis ? roi_w : roi_h, 7.0f);
        float w = 0.0f;
#pragma unroll
        for (int k = 0; k < 14; k++) {
            const float off = (float)(k >> 1) + ((k & 1) ? 0.75f : 0.25f);
            const float ss  = __fadd_rn(start, __fmul_rn(off, sw));
            if (ss > -1.0f && ss < 128.0f) {
                const float sc = fminf(fmaxf(ss, 0.0f), 127.0f);
                const int   i0 = (int)floorf(sc);
                const int   i1 = min(i0 + 1, 127);
                const float l  = sc - (float)i0;
                if (i0 == idx) w += 1.0f - l;
                if (i1 == idx) w += l;
            }
        }
        // deterministic ballot compaction (ascending index order preserved)
        const bool     p    = (w != 0.0f);
        const unsigned m    = __ballot_sync(0xffffffffu, p);
        const int      lane = t & 31;
        const int      warp = t >> 5;
        if (lane == 0) s_warpoff[warp] = __popc(m);
        __syncthreads();
        int off = 0;
        const int wbase = warp & 4;          // warps 0-3: rows, 4-7: cols
        for (int wi = wbase; wi < warp; wi++) off += s_warpoff[wi];
        if (p) {
            const int pos = off + __popc(m & ((1u << lane) - 1));
            if (axis == 0) { s_rows[pos] = idx; s_rw[pos] = w; }
            else           { s_cols[pos] = idx; s_cw[pos] = w; }
        }
        if (lane == 31 && (warp == 3 || warp == 7))
            s_cnt[axis] = off + __popc(m);
    }
    __syncthreads();

    // --- Main accumulation --------------------------------------------------
    const int nr = s_cnt[0], nc = s_cnt[1];
    const int cs = t >> 5;                   // col slice 0..7
    const int ch = (t & 31) * 8;             // 8 channels per thread (uint4 fp16)
    const __half* base = g_nhwc_h + ((size_t)b * HH * WW) * CC + ch;

    float acc[8] = {0.f, 0.f, 0.f, 0.f, 0.f, 0.f, 0.f, 0.f};
    for (int ri = s; ri < nr; ri += NSL) {
        const __half* rowp = base + (size_t)(s_rows[ri] * WW) * CC;
        const float   rw   = s_rw[ri];
#pragma unroll 2
        for (int ci = cs; ci < nc; ci += NCS) {
            const float w = rw * s_cw[ci];
            const uint4 v = *(const uint4*)(rowp + (size_t)s_cols[ci] * CC);
            const __half2* hp = (const __half2*)&v;
#pragma unroll
            for (int k = 0; k < 4; k++) {
                const float2 f = __half22float2(hp[k]);
                acc[2 * k]     = fmaf(w, f.x, acc[2 * k]);
                acc[2 * k + 1] = fmaf(w, f.y, acc[2 * k + 1]);
            }
        }
    }

    float* sp = s_part + cs * CC + ch;
#pragma unroll
    for (int k = 0; k < 8; k++) sp[k] = acc[k];
    __syncthreads();

    // combine 8 col slices -> 256 channel partials -> g_part (deterministic)
    float v = 0.0f;
#pragma unroll
    for (int sl = 0; sl < NCS; sl++) v += s_part[sl * CC + t];
    g_part[((size_t)(roi * NSL + s)) * CC + t] = v;
}

// ---------------------------------------------------------------------------
// Kernel 3: reduce 4 row-slice partials per ROI, scale by 1/196, write out.
// ---------------------------------------------------------------------------
__global__ __launch_bounds__(64) void roi_reduce_kernel(const float* __restrict__ rois,
                                                        float* __restrict__ out) {
    const int roi = blockIdx.x;
    const int t   = threadIdx.x;   // 0..63
    const float4* p = (const float4*)(g_part + (size_t)roi * NSL * CC);
    const float4 a = p[t];
    const float4 b = p[64 + t];
    const float4 c = p[128 + t];
    const float4 d = p[192 + t];
    float4 r;
    r.x = (a.x + b.x + c.x + d.x) * (1.0f / 196.0f);
    r.y = (a.y + b.y + c.y + d.y) * (1.0f / 196.0f);
    r.z = (a.z + b.z + c.z + d.z) * (1.0f / 196.0f);
    r.w = (a.w + b.w + c.w + d.w) * (1.0f / 196.0f);
    ((float4*)(out + (size_t)roi * CC))[t] = r;
    if (t == 0)
        out[(size_t)NROI * CC + roi] = rois[roi * 6 + 1];   // gt = rois[:,1]
}

// ---------------------------------------------------------------------------
extern "C" void kernel_launch(void* const* d_in, const int* in_sizes, int n_in,
                              void* d_out, int out_size) {
    const float* feature_map = (const float*)d_in[0];
    const float* rois        = (const float*)d_in[1];
    float* out = (float*)d_out;

    dim3 tb(32, 8);
    dim3 tg((HH * WW) / 32, CC / 32, BB);      // (512, 8, 4)
    nchw_to_nhwc_h<<<tg, tb>>>(feature_map);

    roi_partial_kernel<<<dim3(NROI, NSL), 256>>>(rois);
    roi_reduce_kernel<<<NROI, 64>>>(rois, out);
    (void)in_sizes; (void)n_in; (void)out_size;
}

// round 9
// speedup vs baseline: 1.6497x; 1.0045x over previous
#include <cuda_runtime.h>
#include <cuda_fp16.h>

#define HH 128
#define WW 128
#define CC 256
#define BB 4
#define NROI 512
#define NSL 8     // row slices  (blockIdx.y)
#define NCS 8     // col slices  (within block)

// 32 MB fp16 NHWC scratch + 4 MB partial-sum buffer (static device globals)
__device__ __half g_nhwc_h[(size_t)BB * HH * WW * CC];
__device__ float  g_part[(size_t)NROI * NSL * CC];

// ---------------------------------------------------------------------------
// Kernel 1: NCHW fp32 -> NHWC fp16 transpose, half2-packed writes.
// Tile: 32 pixels x 64 channels. Load: each thread reads 2 adjacent channel
// planes at one pixel (both 128B-coalesced warp reads), packs to half2,
// stores stile[chpair][pixel]. Write: warp w handles 4 pixels; lane l writes
// channel pair 2l as one uint -> 32 x 4B = 128B full-sector store.
// Bank conflicts: load stores stile[i][tx] (tx varies) - conflict-free;
// write reads stile[l][p] (l varies, stride 33) - conflict-free.
// ---------------------------------------------------------------------------
__global__ __launch_bounds__(256) void nchw_to_nhwc_h2(const float* __restrict__ in) {
    __shared__ unsigned int stile[32][33];   // [channel pair][pixel]
    const int b  = blockIdx.z;
    const int p0 = blockIdx.x * 32;          // pixel tile base (HW dim)
    const int c0 = blockIdx.y * 64;          // channel tile base (64 channels)
    const int tx = threadIdx.x & 31;         // pixel lane
    const int ty = threadIdx.x >> 5;         // 0..7

    const float* src = in + (size_t)b * CC * HH * WW + p0 + tx;
#pragma unroll
    for (int k = 0; k < 4; k++) {
        const int i = ty + 8 * k;            // channel pair index 0..31
        const float f0 = src[(size_t)(c0 + 2 * i)     * (HH * WW)];
        const float f1 = src[(size_t)(c0 + 2 * i + 1) * (HH * WW)];
        const __half2 h = __floats2half2_rn(f0, f1);
        stile[i][tx] = *(const unsigned int*)&h;
    }
    __syncthreads();

    unsigned int* dst = (unsigned int*)(g_nhwc_h + (size_t)b * HH * WW * CC + c0) ;
#pragma unroll
    for (int j = 0; j < 4; j++) {
        const int p = ty * 4 + j;            // pixel within tile 0..31
        dst[((size_t)(p0 + p) * CC) / 2 + tx] = stile[tx][p];
    }
}

// ---------------------------------------------------------------------------
// Kernel 2: block (roi, s) computes partial sums over row-slice s of the ROI
// footprint, all 256 channels, into g_part. Weight lists built in parallel
// (bit-identical FP order to the reference) + deterministic ballot compaction.
// ---------------------------------------------------------------------------
__global__ __launch_bounds__(256, 6) void roi_partial_kernel(const float* __restrict__ rois) {
    const int roi = blockIdx.x;
    const int s   = blockIdx.y;      // row slice 0..NSL-1
    const int t   = threadIdx.x;

    __shared__ int   s_rows[32];
    __shared__ float s_rw[32];
    __shared__ int   s_cols[32];
    __shared__ float s_cw[32];
    __shared__ int   s_cnt[2];
    __shared__ int   s_warpoff[8];
    __shared__ float s_part[NCS * CC];   // 8 KB

    // --- ROI params (every thread, cheap; same FP ops as reference) ---------
    const float* R = rois + roi * 6;
    const int   b   = (int)R[0];
    const float cx  = R[2], cy = R[3], rw_ = R[4], rh_ = R[5];
    const float x1f = __half2float(__float2half_rn((cx - 0.5f * rw_) * 128.0f));
    const float y1f = __half2float(__float2half_rn((cy - 0.5f * rh_) * 128.0f));
    const float x2f = __half2float(__float2half_rn((cx + 0.5f * rw_) * 128.0f));
    const float y2f = __half2float(__float2half_rn((cy + 0.5f * rh_) * 128.0f));
    const float roi_w = fmaxf(x2f - x1f, 1.0f);
    const float roi_h = fmaxf(y2f - y1f, 1.0f);

    // --- Per-thread axis weight: threads 0-127 -> rows, 128-255 -> cols -----
    {
        const int   axis  = t >> 7;          // 0 = y (rows), 1 = x (cols)
        const int   idx   = t & 127;
        const float start = axis ? x1f : y1f;
        const float sw    = __fdiv_rn(axis ? roi_w : roi_h, 7.0f);
        float w = 0.0f;
#pragma unroll
        for (int k = 0; k < 14; k++) {
            const float off = (float)(k >> 1) + ((k & 1) ? 0.75f : 0.25f);
            const float ss  = __fadd_rn(start, __fmul_rn(off, sw));
            if (ss > -1.0f && ss < 128.0f) {
                const float sc = fminf(fmaxf(ss, 0.0f), 127.0f);
                const int   i0 = (int)floorf(sc);
                const int   i1 = min(i0 + 1, 127);
                const float l  = sc - (float)i0;
                if (i0 == idx) w += 1.0f - l;
                if (i1 == idx) w += l;
            }
        }
        // deterministic ballot compaction (ascending index order preserved)
        const bool     p    = (w != 0.0f);
        const unsigned m    = __ballot_sync(0xffffffffu, p);
        const int      lane = t & 31;
        const int      warp = t >> 5;
        if (lane == 0) s_warpoff[warp] = __popc(m);
        __syncthreads();
        int off = 0;
        const int wbase = warp & 4;          // warps 0-3: rows, 4-7: cols
        for (int wi = wbase; wi < warp; wi++) off += s_warpoff[wi];
        if (p) {
            const int pos = off + __popc(m & ((1u << lane) - 1));
            if (axis == 0) { s_rows[pos] = idx; s_rw[pos] = w; }
            else           { s_cols[pos] = idx; s_cw[pos] = w; }
        }
        if (lane == 31 && (warp == 3 || warp == 7))
            s_cnt[axis] = off + __popc(m);
    }
    __syncthreads();

    // --- Main accumulation --------------------------------------------------
    const int nr = s_cnt[0], nc = s_cnt[1];
    const int cs = t >> 5;                   // col slice 0..7
    const int ch = (t & 31) * 8;             // 8 channels per thread (uint4 fp16)
    const __half* base = g_nhwc_h + ((size_t)b * HH * WW) * CC + ch;

    float acc[8] = {0.f, 0.f, 0.f, 0.f, 0.f, 0.f, 0.f, 0.f};
    for (int ri = s; ri < nr; ri += NSL) {
        const __half* rowp = base + (size_t)(s_rows[ri] * WW) * CC;
        const float   rw   = s_rw[ri];
#pragma unroll 2
        for (int ci = cs; ci < nc; ci += NCS) {
            const float w = rw * s_cw[ci];
            const uint4 v = *(const uint4*)(rowp + (size_t)s_cols[ci] * CC);
            const __half2* hp = (const __half2*)&v;
#pragma unroll
            for (int k = 0; k < 4; k++) {
                const float2 f = __half22float2(hp[k]);
                acc[2 * k]     = fmaf(w, f.x, acc[2 * k]);
                acc[2 * k + 1] = fmaf(w, f.y, acc[2 * k + 1]);
            }
        }
    }

    float* sp = s_part + cs * CC + ch;
#pragma unroll
    for (int k = 0; k < 8; k++) sp[k] = acc[k];
    __syncthreads();

    // combine 8 col slices -> 256 channel partials -> g_part (deterministic)
    float v = 0.0f;
#pragma unroll
    for (int sl = 0; sl < NCS; sl++) v += s_part[sl * CC + t];
    g_part[((size_t)(roi * NSL + s)) * CC + t] = v;
}

// ---------------------------------------------------------------------------
// Kernel 3: reduce NSL row-slice partials per ROI, scale by 1/196, write out.
// ---------------------------------------------------------------------------
__global__ __launch_bounds__(64) void roi_reduce_kernel(const float* __restrict__ rois,
                                                        float* __restrict__ out) {
    const int roi = blockIdx.x;
    const int t   = threadIdx.x;   // 0..63
    const float4* p = (const float4*)(g_part + (size_t)roi * NSL * CC);
    float4 r = make_float4(0.f, 0.f, 0.f, 0.f);
#pragma unroll
    for (int sl = 0; sl < NSL; sl++) {
        const float4 a = p[sl * 64 + t];
        r.x += a.x; r.y += a.y; r.z += a.z; r.w += a.w;
    }
    r.x *= (1.0f / 196.0f);
    r.y *= (1.0f / 196.0f);
    r.z *= (1.0f / 196.0f);
    r.w *= (1.0f / 196.0f);
    ((float4*)(out + (size_t)roi * CC))[t] = r;
    if (t == 0)
        out[(size_t)NROI * CC + roi] = rois[roi * 6 + 1];   // gt = rois[:,1]
}

// ---------------------------------------------------------------------------
extern "C" void kernel_launch(void* const* d_in, const int* in_sizes, int n_in,
                              void* d_out, int out_size) {
    const float* feature_map = (const float*)d_in[0];
    const float* rois        = (const float*)d_in[1];
    float* out = (float*)d_out;

    dim3 tg((HH * WW) / 32, CC / 64, BB);      // (512, 4, 4)
    nchw_to_nhwc_h2<<<tg, 256>>>(feature_map);

    roi_partial_kernel<<<dim3(NROI, NSL), 256>>>(rois);
    roi_reduce_kernel<<<NROI, 64>>>(rois, out);
    (void)in_sizes; (void)n_in; (void)out_size;
}

// round 11
// speedup vs baseline: 1.8755x; 1.1369x over previous
#include <cuda_runtime.h>
#include <cuda_fp16.h>

#define HH 128
#define WW 128
#define CC 256
#define BB 4
#define NROI 512
#define NSL 4     // row-slice blocks per ROI

// 32 MB fp16 NHWC scratch + 2 MB partial-sum buffer (static device globals)
__device__ __half g_nhwc_h[(size_t)BB * HH * WW * CC];
__device__ float  g_part[(size_t)NROI * NSL * CC];

// ---------------------------------------------------------------------------
// Kernel 1: NCHW fp32 -> NHWC fp16 transpose, half2-packed full-sector writes.
// (unchanged from R9: measured 16.4us)
// ---------------------------------------------------------------------------
__global__ __launch_bounds__(256) void nchw_to_nhwc_h2(const float* __restrict__ in) {
    __shared__ unsigned int stile[32][33];   // [channel pair][pixel]
    const int b  = blockIdx.z;
    const int p0 = blockIdx.x * 32;          // pixel tile base (HW dim)
    const int c0 = blockIdx.y * 64;          // channel tile base (64 channels)
    const int tx = threadIdx.x & 31;         // pixel lane
    const int ty = threadIdx.x >> 5;         // 0..7

    const float* src = in + (size_t)b * CC * HH * WW + p0 + tx;
#pragma unroll
    for (int k = 0; k < 4; k++) {
        const int i = ty + 8 * k;            // channel pair index 0..31
        const float f0 = src[(size_t)(c0 + 2 * i)     * (HH * WW)];
        const float f1 = src[(size_t)(c0 + 2 * i + 1) * (HH * WW)];
        const __half2 h = __floats2half2_rn(f0, f1);
        stile[i][tx] = *(const unsigned int*)&h;
    }
    __syncthreads();

    unsigned int* dst = (unsigned int*)(g_nhwc_h + (size_t)b * HH * WW * CC + c0);
#pragma unroll
    for (int j = 0; j < 4; j++) {
        const int p = ty * 4 + j;            // pixel within tile 0..31
        dst[((size_t)(p0 + p) * CC) / 2 + tx] = stile[tx][p];
    }
}

// ---------------------------------------------------------------------------
// Kernel 2: block (roi, s). The ROI footprint (nr x nc cells) is flattened to
// npx pixels; 32 contiguous, balanced pixel ranges are assigned to the 32
// warps across the 4 blocks of this ROI (range q = s*8 + warp). Lanes carry 8
// channels each (one uint4 per pixel). 4 independent loads batched per
// iteration for MLP; 64-reg budget via __launch_bounds__(256,4).
// ---------------------------------------------------------------------------
__global__ __launch_bounds__(256, 4) void roi_partial_kernel(const float* __restrict__ rois) {
    const int roi  = blockIdx.x;
    const int s    = blockIdx.y;     // 0..3
    const int t    = threadIdx.x;
    const int lane = t & 31;
    const int wrp  = t >> 5;         // 0..7

    __shared__ int   s_rows[32];
    __shared__ float s_rw[32];
    __shared__ int   s_cols[32];
    __shared__ float s_cw[32];
    __shared__ int   s_cnt[2];
    __shared__ int   s_warpoff[8];
    __shared__ float s_red[8][CC];   // 8 KB

    // --- ROI params (every thread; same FP ops as reference) ----------------
    const float* R = rois + roi * 6;
    const int   b   = (int)R[0];
    const float cx  = R[2], cy = R[3], rw_ = R[4], rh_ = R[5];
    const float x1f = __half2float(__float2half_rn((cx - 0.5f * rw_) * 128.0f));
    const float y1f = __half2float(__float2half_rn((cy - 0.5f * rh_) * 128.0f));
    const float x2f = __half2float(__float2half_rn((cx + 0.5f * rw_) * 128.0f));
    const float y2f = __half2float(__float2half_rn((cy + 0.5f * rh_) * 128.0f));
    const float roi_w = fmaxf(x2f - x1f, 1.0f);
    const float roi_h = fmaxf(y2f - y1f, 1.0f);

    // --- Per-thread axis weight: threads 0-127 -> rows, 128-255 -> cols -----
    {
        const int   axis  = t >> 7;
        const int   idx   = t & 127;
        const float start = axis ? x1f : y1f;
        const float sw    = __fdiv_rn(axis ? roi_w : roi_h, 7.0f);
        float w = 0.0f;
#pragma unroll
        for (int k = 0; k < 14; k++) {
            const float off = (float)(k >> 1) + ((k & 1) ? 0.75f : 0.25f);
            const float ss  = __fadd_rn(start, __fmul_rn(off, sw));
            if (ss > -1.0f && ss < 128.0f) {
                const float sc = fminf(fmaxf(ss, 0.0f), 127.0f);
                const int   i0 = (int)floorf(sc);
                const int   i1 = min(i0 + 1, 127);
                const float l  = sc - (float)i0;
                if (i0 == idx) w += 1.0f - l;
                if (i1 == idx) w += l;
            }
        }
        const bool     p    = (w != 0.0f);
        const unsigned m    = __ballot_sync(0xffffffffu, p);
        if (lane == 0) s_warpoff[wrp] = __popc(m);
        __syncthreads();
        int off = 0;
        const int wbase = wrp & 4;           // warps 0-3: rows, 4-7: cols
        for (int wi = wbase; wi < wrp; wi++) off += s_warpoff[wi];
        if (p) {
            const int pos = off + __popc(m & ((1u << lane) - 1));
            if (axis == 0) { s_rows[pos] = idx; s_rw[pos] = w; }
            else           { s_cols[pos] = idx; s_cw[pos] = w; }
        }
        if (lane == 31 && (wrp == 3 || wrp == 7))
            s_cnt[axis] = off + __popc(m);
    }
    __syncthreads();

    // --- Balanced contiguous pixel range for this warp ----------------------
    const int nr  = s_cnt[0], nc = s_cnt[1];
    const int npx = nr * nc;                       // <= 784
    const int q   = s * 8 + wrp;                   // slice 0..31
    const int lo  = (npx * q) >> 5;
    const int hi  = (npx * (q + 1)) >> 5;

    const int ch = lane * 8;
    const __half* base = g_nhwc_h + ((size_t)b * HH * WW) * CC + ch;

    float acc[8] = {0.f, 0.f, 0.f, 0.f, 0.f, 0.f, 0.f, 0.f};
    if (lo < hi) {
        int r = lo / nc;
        int c = lo - r * nc;
        const __half* rowp = base + (size_t)(s_rows[r] * WW) * CC;
        float rwt = s_rw[r];
        int i = lo;

        // main: 4 independent pixel loads in flight
        for (; i + 4 <= hi; i += 4) {
            float wt[4];
            uint4 v[4];
#pragma unroll
            for (int u = 0; u < 4; u++) {
                wt[u] = rwt * s_cw[c];
                v[u]  = *(const uint4*)(rowp + (size_t)s_cols[c] * CC);
                if (++c == nc) {
                    c = 0;
                    if (++r < nr) {
                        rowp = base + (size_t)(s_rows[r] * WW) * CC;
                        rwt  = s_rw[r];
                    }
                }
            }
#pragma unroll
            for (int u = 0; u < 4; u++) {
                const __half2* hp = (const __half2*)&v[u];
#pragma unroll
                for (int k = 0; k < 4; k++) {
                    const float2 f = __half22float2(hp[k]);
                    acc[2 * k]     = fmaf(wt[u], f.x, acc[2 * k]);
                    acc[2 * k + 1] = fmaf(wt[u], f.y, acc[2 * k + 1]);
                }
            }
        }
        // tail
        for (; i < hi; i++) {
            const float wt = rwt * s_cw[c];
            const uint4 v  = *(const uint4*)(rowp + (size_t)s_cols[c] * CC);
            const __half2* hp = (const __half2*)&v;
#pragma unroll
            for (int k = 0; k < 4; k++) {
                const float2 f = __half22float2(hp[k]);
                acc[2 * k]     = fmaf(wt, f.x, acc[2 * k]);
                acc[2 * k + 1] = fmaf(wt, f.y, acc[2 * k + 1]);
            }
            if (++c == nc) {
                c = 0;
                if (++r < nr) {
                    rowp = base + (size_t)(s_rows[r] * WW) * CC;
                    rwt  = s_rw[r];
                }
            }
        }
    }

    float* sp = &s_red[wrp][ch];
#pragma unroll
    for (int k = 0; k < 8; k++) sp[k] = acc[k];
    __syncthreads();

    // combine 8 warp slices -> 256 channel partials (deterministic order)
    float vsum = 0.0f;
#pragma unroll
    for (int sl = 0; sl < 8; sl++) vsum += s_red[sl][t];
    g_part[((size_t)(roi * NSL + s)) * CC + t] = vsum;
}

// ---------------------------------------------------------------------------
// Kernel 3: reduce NSL row-slice partials per ROI, scale by 1/196, write out.
// ---------------------------------------------------------------------------
__global__ __launch_bounds__(64) void roi_reduce_kernel(const float* __restrict__ rois,
                                                        float* __restrict__ out) {
    const int roi = blockIdx.x;
    const int t   = threadIdx.x;   // 0..63
    const float4* p = (const float4*)(g_part + (size_t)roi * NSL * CC);
    float4 r = make_float4(0.f, 0.f, 0.f, 0.f);
#pragma unroll
    for (int sl = 0; sl < NSL; sl++) {
        const float4 a = p[sl * 64 + t];
        r.x += a.x; r.y += a.y; r.z += a.z; r.w += a.w;
    }
    r.x *= (1.0f / 196.0f);
    r.y *= (1.0f / 196.0f);
    r.z *= (1.0f / 196.0f);
    r.w *= (1.0f / 196.0f);
    ((float4*)(out + (size_t)roi * CC))[t] = r;
    if (t == 0)
        out[(size_t)NROI * CC + roi] = rois[roi * 6 + 1];   // gt = rois[:,1]
}

// ---------------------------------------------------------------------------
extern "C" void kernel_launch(void* const* d_in, const int* in_sizes, int n_in,
                              void* d_out, int out_size) {
    const float* feature_map = (const float*)d_in[0];
    const float* rois        = (const float*)d_in[1];
    float* out = (float*)d_out;

    dim3 tg((HH * WW) / 32, CC / 64, BB);      // (512, 4, 4)
    nchw_to_nhwc_h2<<<tg, 256>>>(feature_map);

    roi_partial_kernel<<<dim3(NROI, NSL), 256>>>(rois);
    roi_reduce_kernel<<<NROI, 64>>>(rois, out);
    (void)in_sizes; (void)n_in; (void)out_size;
}

// round 12
// speedup vs baseline: 1.9784x; 1.0548x over previous
#include <cuda_runtime.h>
#include <cuda_fp16.h>

#define HH 128
#define WW 128
#define CC 256
#define BB 4
#define NROI 512
#define NSL 4     // row-slice blocks per ROI
#define UB  6     // pixel batch (loads in flight per thread)

// 32 MB fp16 NHWC scratch + 2 MB partial-sum buffer (static device globals)
__device__ __half g_nhwc_h[(size_t)BB * HH * WW * CC];
__device__ float  g_part[(size_t)NROI * NSL * CC];

// ---------------------------------------------------------------------------
// Kernel 1 (v3): NCHW fp32 -> NHWC fp16 transpose.
// Tile: 128 pixels x 64 channels. Each thread: 4 channel pairs, loading
// float4 (4 pixels) from each of 2 planes via __ldcs (streaming: input is
// read-once, keep L2 for the scratch). 128 B per thread in flight.
// smem stile[pair][pixel], row stride 129 words -> write-phase LDS reads
// stile[lane][p] conflict-free; store side has inherent 4-way phasing
// (4 consecutive words per lane), acceptable within the DRAM budget.
// Write: warp ty covers pixels 16ty..16ty+15; lane l stores channel pair l
// as one uint -> 32 x 4B = 128 B full-sector STG per op.
// ---------------------------------------------------------------------------
__global__ __launch_bounds__(256) void nchw_to_nhwc_h3(const float* __restrict__ in) {
    __shared__ unsigned int stile[32][129];  // [channel pair][pixel 0..127]
    const int b  = blockIdx.z;
    const int p0 = blockIdx.x * 128;         // pixel tile base (HW dim)
    const int c0 = blockIdx.y * 64;          // channel tile base (64 channels)
    const int tx = threadIdx.x & 31;
    const int ty = threadIdx.x >> 5;         // 0..7

    const size_t bOff = (size_t)b * CC * (HH * WW);
#pragma unroll
    for (int k = 0; k < 4; k++) {
        const int i = ty + 8 * k;            // channel pair 0..31
        const float4* pa = (const float4*)(in + bOff + (size_t)(c0 + 2 * i)     * (HH * WW) + p0);
        const float4* pb = (const float4*)(in + bOff + (size_t)(c0 + 2 * i + 1) * (HH * WW) + p0);
        const float4 a  = __ldcs(pa + tx);   // pixels 4tx..4tx+3, plane c0+2i
        const float4 b4 = __ldcs(pb + tx);   // same pixels, plane c0+2i+1
        const __half2 h0 = __floats2half2_rn(a.x, b4.x);
        const __half2 h1 = __floats2half2_rn(a.y, b4.y);
        const __half2 h2 = __floats2half2_rn(a.z, b4.z);
        const __half2 h3 = __floats2half2_rn(a.w, b4.w);
        stile[i][4 * tx + 0] = *(const unsigned int*)&h0;
        stile[i][4 * tx + 1] = *(const unsigned int*)&h1;
        stile[i][4 * tx + 2] = *(const unsigned int*)&h2;
        stile[i][4 * tx + 3] = *(const unsigned int*)&h3;
    }
    __syncthreads();

    unsigned int* dstbase = (unsigned int*)g_nhwc_h + ((size_t)b * (HH * WW)) * (CC / 2) + (c0 >> 1);
#pragma unroll
    for (int j = 0; j < 16; j++) {
        const int p = ty * 16 + j;           // pixel within tile 0..127
        dstbase[(size_t)(p0 + p) * (CC / 2) + tx] = stile[tx][p];
    }
}

// ---------------------------------------------------------------------------
// Kernel 2: block (roi, s). Footprint (nr x nc) flattened to npx pixels; 32
// contiguous balanced ranges over 4 blocks x 8 warps. Lanes carry 8 channels
// (uint4). UB independent loads in flight; 64-reg budget.
// ---------------------------------------------------------------------------
__global__ __launch_bounds__(256, 4) void roi_partial_kernel(const float* __restrict__ rois) {
    const int roi  = blockIdx.x;
    const int s    = blockIdx.y;     // 0..3
    const int t    = threadIdx.x;
    const int lane = t & 31;
    const int wrp  = t >> 5;         // 0..7

    __shared__ int   s_rows[32];
    __shared__ float s_rw[32];
    __shared__ int   s_cols[32];
    __shared__ float s_cw[32];
    __shared__ int   s_cnt[2];
    __shared__ int   s_warpoff[8];
    __shared__ float s_red[8][CC];   // 8 KB

    // --- ROI params (every thread; same FP ops as reference) ----------------
    const float* R = rois + roi * 6;
    const int   b   = (int)R[0];
    const float cx  = R[2], cy = R[3], rw_ = R[4], rh_ = R[5];
    const float x1f = __half2float(__float2half_rn((cx - 0.5f * rw_) * 128.0f));
    const float y1f = __half2float(__float2half_rn((cy - 0.5f * rh_) * 128.0f));
    const float x2f = __half2float(__float2half_rn((cx + 0.5f * rw_) * 128.0f));
    const float y2f = __half2float(__float2half_rn((cy + 0.5f * rh_) * 128.0f));
    const float roi_w = fmaxf(x2f - x1f, 1.0f);
    const float roi_h = fmaxf(y2f - y1f, 1.0f);

    // --- Per-thread axis weight: threads 0-127 -> rows, 128-255 -> cols -----
    {
        const int   axis  = t >> 7;
        const int   idx   = t & 127;
        const float start = axis ? x1f : y1f;
        const float sw    = __fdiv_rn(axis ? roi_w : roi_h, 7.0f);
        float w = 0.0f;
#pragma unroll
        for (int k = 0; k < 14; k++) {
            const float off = (float)(k >> 1) + ((k & 1) ? 0.75f : 0.25f);
            const float ss  = __fadd_rn(start, __fmul_rn(off, sw));
            if (ss > -1.0f && ss < 128.0f) {
                const float sc = fminf(fmaxf(ss, 0.0f), 127.0f);
                const int   i0 = (int)floorf(sc);
                const int   i1 = min(i0 + 1, 127);
                const float l  = sc - (float)i0;
                if (i0 == idx) w += 1.0f - l;
                if (i1 == idx) w += l;
            }
        }
        const bool     p    = (w != 0.0f);
        const unsigned m    = __ballot_sync(0xffffffffu, p);
        if (lane == 0) s_warpoff[wrp] = __popc(m);
        __syncthreads();
        int off = 0;
        const int wbase = wrp & 4;           // warps 0-3: rows, 4-7: cols
        for (int wi = wbase; wi < wrp; wi++) off += s_warpoff[wi];
        if (p) {
            const int pos = off + __popc(m & ((1u << lane) - 1));
            if (axis == 0) { s_rows[pos] = idx; s_rw[pos] = w; }
            else           { s_cols[pos] = idx; s_cw[pos] = w; }
        }
        if (lane == 31 && (wrp == 3 || wrp == 7))
            s_cnt[axis] = off + __popc(m);
    }
    __syncthreads();

    // --- Balanced contiguous pixel range for this warp ----------------------
    const int nr  = s_cnt[0], nc = s_cnt[1];
    const int npx = nr * nc;                       // <= 784
    const int q   = s * 8 + wrp;                   // slice 0..31
    const int lo  = (npx * q) >> 5;
    const int hi  = (npx * (q + 1)) >> 5;

    const int ch = lane * 8;
    const __half* base = g_nhwc_h + ((size_t)b * HH * WW) * CC + ch;

    float acc[8] = {0.f, 0.f, 0.f, 0.f, 0.f, 0.f, 0.f, 0.f};
    if (lo < hi) {
        int r = lo / nc;
        int c = lo - r * nc;
        const __half* rowp = base + (size_t)(s_rows[r] * WW) * CC;
        float rwt = s_rw[r];
        int i = lo;

        // main: UB independent pixel loads in flight
        for (; i + UB <= hi; i += UB) {
            float wt[UB];
            uint4 v[UB];
#pragma unroll
            for (int u = 0; u < UB; u++) {
                wt[u] = rwt * s_cw[c];
                v[u]  = *(const uint4*)(rowp + (size_t)s_cols[c] * CC);
                if (++c == nc) {
                    c = 0;
                    if (++r < nr) {
                        rowp = base + (size_t)(s_rows[r] * WW) * CC;
                        rwt  = s_rw[r];
                    }
                }
            }
#pragma unroll
            for (int u = 0; u < UB; u++) {
                const __half2* hp = (const __half2*)&v[u];
#pragma unroll
                for (int k = 0; k < 4; k++) {
                    const float2 f = __half22float2(hp[k]);
                    acc[2 * k]     = fmaf(wt[u], f.x, acc[2 * k]);
                    acc[2 * k + 1] = fmaf(wt[u], f.y, acc[2 * k + 1]);
                }
            }
        }
        // tail
        for (; i < hi; i++) {
            const float wt = rwt * s_cw[c];
            const uint4 v  = *(const uint4*)(rowp + (size_t)s_cols[c] * CC);
            const __half2* hp = (const __half2*)&v;
#pragma unroll
            for (int k = 0; k < 4; k++) {
                const float2 f = __half22float2(hp[k]);
                acc[2 * k]     = fmaf(wt, f.x, acc[2 * k]);
                acc[2 * k + 1] = fmaf(wt, f.y, acc[2 * k + 1]);
            }
            if (++c == nc) {
                c = 0;
                if (++r < nr) {
                    rowp = base + (size_t)(s_rows[r] * WW) * CC;
                    rwt  = s_rw[r];
                }
            }
        }
    }

    float* sp = &s_red[wrp][ch];
#pragma unroll
    for (int k = 0; k < 8; k++) sp[k] = acc[k];
    __syncthreads();

    // combine 8 warp slices -> 256 channel partials (deterministic order)
    float vsum = 0.0f;
#pragma unroll
    for (int sl = 0; sl < 8; sl++) vsum += s_red[sl][t];
    g_part[((size_t)(roi * NSL + s)) * CC + t] = vsum;
}

// ---------------------------------------------------------------------------
// Kernel 3: reduce NSL row-slice partials per ROI, scale by 1/196, write out.
// ---------------------------------------------------------------------------
__global__ __launch_bounds__(64) void roi_reduce_kernel(const float* __restrict__ rois,
                                                        float* __restrict__ out) {
    const int roi = blockIdx.x;
    const int t   = threadIdx.x;   // 0..63
    const float4* p = (const float4*)(g_part + (size_t)roi * NSL * CC);
    float4 r = make_float4(0.f, 0.f, 0.f, 0.f);
#pragma unroll
    for (int sl = 0; sl < NSL; sl++) {
        const float4 a = p[sl * 64 + t];
        r.x += a.x; r.y += a.y; r.z += a.z; r.w += a.w;
    }
    r.x *= (1.0f / 196.0f);
    r.y *= (1.0f / 196.0f);
    r.z *= (1.0f / 196.0f);
    r.w *= (1.0f / 196.0f);
    ((float4*)(out + (size_t)roi * CC))[t] = r;
    if (t == 0)
        out[(size_t)NROI * CC + roi] = rois[roi * 6 + 1];   // gt = rois[:,1]
}

// ---------------------------------------------------------------------------
extern "C" void kernel_launch(void* const* d_in, const int* in_sizes, int n_in,
                              void* d_out, int out_size) {
    const float* feature_map = (const float*)d_in[0];
    const float* rois        = (const float*)d_in[1];
    float* out = (float*)d_out;

    dim3 tg((HH * WW) / 128, CC / 64, BB);     // (128, 4, 4)
    nchw_to_nhwc_h3<<<tg, 256>>>(feature_map);

    roi_partial_kernel<<<dim3(NROI, NSL), 256>>>(rois);
    roi_reduce_kernel<<<NROI, 64>>>(rois, out);
    (void)in_sizes; (void)n_in; (void)out_size;
}